// round 15
// baseline (speedup 1.0000x reference)
#include <cuda_runtime.h>
#include <cuda_fp16.h>
#include <cstdint>

#define N_NODES 50000
#define N_EDGES 400000
#define D_IN    256
#define D_HID   512
#define D_OUT   128
#define N_LAYERS 4
#define SCAN_NB 49   // ceil(50000/1024)

// ---------------------------------------------------------------------------
// Scratch (__device__ globals; allocation-free rule)
// ---------------------------------------------------------------------------
__device__ __align__(16) __half g_hw[(size_t)N_NODES * D_HID];
__device__ float g_dinv[N_NODES];
__device__ __align__(16) __half g_a[(size_t)N_NODES * D_HID];   // x fp16
__device__ __align__(16) __half g_b[(size_t)N_NODES * D_HID];   // h fp16
// CSR
__device__ int g_rowcnt[N_NODES];
__device__ int g_cursor[N_NODES];
__device__ int g_rowptr[N_NODES + 1];
__device__ int g_bsum[64];
__device__ int g_csrsrc[N_EDGES];
// transposed weights, fp16: W1T[512,256] | WcT[4][512,512] | W2T[128,512]
#define W1T_OFF 0
#define WCT_OFF (D_HID * D_IN)
#define W2T_OFF (WCT_OFF + N_LAYERS * D_HID * D_HID)
#define W_TOTAL (W2T_OFF + D_OUT * D_HID)
__device__ __align__(16) __half g_whi[W_TOTAL];

// ---------------------------------------------------------------------------
static __device__ __forceinline__ uint32_t smem_u32(const void* p) {
    uint32_t a;
    asm("{ .reg .u64 t; cvta.to.shared.u64 t, %1; cvt.u32.u64 %0, t; }" : "=r"(a) : "l"(p));
    return a;
}

#define CP_ASYNC16(dst, src) \
    asm volatile("cp.async.cg.shared.global [%0], [%1], 16;" :: "r"(dst), "l"(src) : "memory")
#define CP_COMMIT() asm volatile("cp.async.commit_group;" ::: "memory")
#define CP_WAIT1()  asm volatile("cp.async.wait_group 1;"  ::: "memory")

#define LDMATRIX_X4(r0, r1, r2, r3, addr) \
    asm volatile("ldmatrix.sync.aligned.m8n8.x4.shared.b16 {%0,%1,%2,%3}, [%4];" \
                 : "=r"(r0), "=r"(r1), "=r"(r2), "=r"(r3) : "r"(addr))

#define MMA16816(c0, c1, c2, c3, a0, a1, a2, a3, b0, b1) \
    asm volatile("mma.sync.aligned.m16n8k16.row.col.f32.f16.f16.f32 " \
                 "{%0,%1,%2,%3}, {%4,%5,%6,%7}, {%8,%9}, {%0,%1,%2,%3};" \
                 : "+f"(c0), "+f"(c1), "+f"(c2), "+f"(c3) \
                 : "r"(a0), "r"(a1), "r"(a2), "r"(a3), "r"(b0), "r"(b1))

// ---------------------------------------------------------------------------
// CSR build + dinv
// ---------------------------------------------------------------------------
__global__ void hist_zero_kernel(int* __restrict__ cnt, int* __restrict__ cur) {
    int n = blockIdx.x * blockDim.x + threadIdx.x;
    if (n < N_NODES) { cnt[n] = 0; cur[n] = 0; }
}
__global__ void hist_kernel(const int* __restrict__ dst, int* __restrict__ cnt) {
    int e = blockIdx.x * blockDim.x + threadIdx.x;
    if (e < N_EDGES) atomicAdd(&cnt[dst[e]], 1);
}
__global__ void scan_local_kernel(const int* __restrict__ cnt, int* __restrict__ rptr,
                                  int* __restrict__ bsum) {
    __shared__ int sh[1024];
    int t = threadIdx.x;
    int i = blockIdx.x * 1024 + t;
    int v = (i < N_NODES) ? cnt[i] : 0;
    sh[t] = v;
    __syncthreads();
    #pragma unroll
    for (int off = 1; off < 1024; off <<= 1) {
        int x = 0;
        if (t >= off) x = sh[t - off];
        __syncthreads();
        if (t >= off) sh[t] += x;
        __syncthreads();
    }
    if (i < N_NODES) rptr[i] = sh[t] - v;   // exclusive
    if (t == 1023) bsum[blockIdx.x] = sh[1023];
}
// fused: add block prefix + rowptr[N] + dinv (integer-exact vs 3-kernel chain)
__global__ void scan_finish_kernel(int* __restrict__ rptr, const int* __restrict__ bsum,
                                   const int* __restrict__ cnt, float* __restrict__ dinv) {
    int i = blockIdx.x * blockDim.x + threadIdx.x;
    if (i < N_NODES) {
        int g = i >> 10;
        int pre = 0;
        for (int b = 0; b < g; b++) pre += bsum[b];
        rptr[i] += pre;
        dinv[i] = rsqrtf((float)cnt[i] + 1.0f);
    }
    if (i == 0) rptr[N_NODES] = N_EDGES;
}
__global__ void fill_kernel(const int* __restrict__ src, const int* __restrict__ dst,
                            const int* __restrict__ rptr, int* __restrict__ cur,
                            int* __restrict__ csrsrc) {
    int e = blockIdx.x * blockDim.x + threadIdx.x;
    if (e >= N_EDGES) return;
    int d = dst[e];
    int pos = rptr[d] + atomicAdd(&cur[d], 1);
    csrsrc[pos] = src[e];
}
// Sort each CSR row ascending -> deterministic aggregation order regardless of
// the atomic fill order. One thread per row (degree ~8, insertion sort).
__global__ void sort_rows_kernel(const int* __restrict__ rowptr, int* __restrict__ csrsrc) {
    int n = blockIdx.x * blockDim.x + threadIdx.x;
    if (n >= N_NODES) return;
    int e0 = rowptr[n], e1 = rowptr[n + 1];
    for (int i = e0 + 1; i < e1; i++) {
        int v = csrsrc[i];
        int j = i - 1;
        while (j >= e0 && csrsrc[j] > v) { csrsrc[j + 1] = csrsrc[j]; j--; }
        csrsrc[j + 1] = v;
    }
}

// ---------------------------------------------------------------------------
// x fp32 -> fp16
// ---------------------------------------------------------------------------
__global__ void conv_x_kernel(const float* __restrict__ in,
                              __half* __restrict__ o, long long n4) {
    long long i = (long long)blockIdx.x * blockDim.x + threadIdx.x;
    if (i >= n4) return;
    float4 v = reinterpret_cast<const float4*>(in)[i];
    __half2 lo = __floats2half2_rn(v.x, v.y);
    __half2 hi = __floats2half2_rn(v.z, v.w);
    reinterpret_cast<uint2*>(o)[i] =
        make_uint2(*reinterpret_cast<uint32_t*>(&lo), *reinterpret_cast<uint32_t*>(&hi));
}

// ALL weights fp32 -> transposed fp16 in one launch (integer-exact mapping).
__global__ void conv_w_all_kernel(const float* __restrict__ W1,
                                  const float* __restrict__ Wc,
                                  const float* __restrict__ W2,
                                  __half* __restrict__ o) {
    int idx = blockIdx.x * blockDim.x + threadIdx.x;
    if (idx >= W_TOTAL) return;
    const float* src;
    int K, N, local, segoff;
    if (idx < WCT_OFF) {                       // W1: [256,512]
        src = W1; K = D_IN; N = D_HID; local = idx; segoff = W1T_OFF;
    } else if (idx < W2T_OFF) {                // Wc[l]: [512,512]
        int t = idx - WCT_OFF;
        int l = t / (D_HID * D_HID);
        local = t - l * D_HID * D_HID;
        src = Wc + (size_t)l * D_HID * D_HID;
        K = D_HID; N = D_HID; segoff = WCT_OFF + l * D_HID * D_HID;
    } else {                                   // W2: [512,128]
        src = W2; K = D_HID; N = D_OUT; local = idx - W2T_OFF; segoff = W2T_OFF;
    }
    int k = local / N, n = local - k * N;
    o[segoff + (size_t)n * K + k] = __float2half_rn(src[local]);
}

// ---------------------------------------------------------------------------
// HMMA fp16 GEMM, single pass: C = A @ B^T.
// 2-STAGE cp.async pipeline — the configuration proven clean across R5-R10
// (the 3-stage variant showed timing-dependent nondeterminism; reverted).
// MODE 0: dnn1 — bias+relu, write fp16
// MODE 1: conv — write fp16 C (hw)
// MODE 2: dnn2 — bias, write fp32 C
// ---------------------------------------------------------------------------
#define STAGE_BYTES 16384

template<int KDIM, int MODE>
__global__ void __launch_bounds__(256, 2)
gemm_mma_kernel(const __half* __restrict__ A, const __half* __restrict__ B,
                const float* __restrict__ bias,
                float* __restrict__ Cf, __half* __restrict__ Ch,
                int M, int N) {
    __shared__ __align__(1024) char smem[2 * STAGE_BYTES];
    const uint32_t sbase = smem_u32(smem);

    const int tid  = threadIdx.x;
    const int lane = tid & 31;
    const int wid  = tid >> 5;
    const int wm   = wid >> 2;
    const int wn   = wid & 3;
    const int gq   = lane >> 2;
    const int tq   = lane & 3;
    const int row0 = blockIdx.x * 128;
    const int col0 = blockIdx.y * 128;

    constexpr int NC = KDIM / 32;

    if (row0 + 127 >= M) {
        for (int f = tid; f < 512; f += 256) {
            int r = f >> 2, kq = f & 3;
            if (row0 + r >= M) {
                uint32_t off = (uint32_t)(r * 64 + ((kq ^ ((r >> 1) & 3)) * 16));
                asm volatile("st.shared.v4.b32 [%0], {%1,%1,%1,%1};" :: "r"(sbase + off), "r"(0u));
                asm volatile("st.shared.v4.b32 [%0], {%1,%1,%1,%1};" :: "r"(sbase + STAGE_BYTES + off), "r"(0u));
            }
        }
        __syncthreads();
    }

    float acc[4][4][4];
    #pragma unroll
    for (int i = 0; i < 4; i++)
        #pragma unroll
        for (int j = 0; j < 4; j++)
            #pragma unroll
            for (int q = 0; q < 4; q++) acc[i][j][q] = 0.0f;

    auto load_stage = [&](int stage, int chunk) {
        const int k0 = chunk * 32;
        const uint32_t sA = sbase + stage * STAGE_BYTES;
        const uint32_t sB = sA + 8192;
        #pragma unroll
        for (int f = tid; f < 512; f += 256) {
            int r = f >> 2, kq = f & 3;
            uint32_t off = (uint32_t)(r * 64 + ((kq ^ ((r >> 1) & 3)) * 16));
            int gr = row0 + r;
            if (gr < M) CP_ASYNC16(sA + off, A + (size_t)gr * KDIM + k0 + kq * 8);
            CP_ASYNC16(sB + off, B + (size_t)(col0 + r) * KDIM + k0 + kq * 8);
        }
    };

    load_stage(0, 0);
    CP_COMMIT();

    for (int c = 0; c < NC; c++) {
        if (c + 1 < NC) load_stage((c + 1) & 1, c + 1);
        CP_COMMIT();
        CP_WAIT1();
        __syncthreads();

        const uint32_t sA = sbase + (c & 1) * STAGE_BYTES;
        const uint32_t sB = sA + 8192;

        #pragma unroll
        for (int ks = 0; ks < 2; ks++) {
            uint32_t a[4][4];
            #pragma unroll
            for (int mt = 0; mt < 4; mt++) {
                int r  = wm * 64 + mt * 16 + (lane & 15);
                int kq = (2 * ks + (lane >> 4)) ^ ((r >> 1) & 3);
                LDMATRIX_X4(a[mt][0], a[mt][1], a[mt][2], a[mt][3],
                            sA + (uint32_t)(r * 64 + kq * 16));
            }
            uint32_t b[4][2];
            #pragma unroll
            for (int pr = 0; pr < 2; pr++) {
                int r  = wn * 32 + pr * 16 + ((lane >> 4) & 1) * 8 + (lane & 7);
                int kq = (2 * ks + ((lane >> 3) & 1)) ^ ((r >> 1) & 3);
                LDMATRIX_X4(b[pr * 2][0], b[pr * 2][1], b[pr * 2 + 1][0], b[pr * 2 + 1][1],
                            sB + (uint32_t)(r * 64 + kq * 16));
            }
            #pragma unroll
            for (int mt = 0; mt < 4; mt++)
                #pragma unroll
                for (int nt = 0; nt < 4; nt++)
                    MMA16816(acc[mt][nt][0], acc[mt][nt][1], acc[mt][nt][2], acc[mt][nt][3],
                             a[mt][0], a[mt][1], a[mt][2], a[mt][3],
                             b[nt][0], b[nt][1]);
        }
        __syncthreads();
    }

    // epilogue
    #pragma unroll
    for (int mt = 0; mt < 4; mt++) {
        int r0 = row0 + wm * 64 + mt * 16 + gq;
        int r1 = r0 + 8;
        #pragma unroll
        for (int nt = 0; nt < 4; nt++) {
            int gc = col0 + wn * 32 + nt * 8 + tq * 2;
            float2 bb = make_float2(0.f, 0.f);
            if (MODE != 1) bb = *reinterpret_cast<const float2*>(&bias[gc]);
            float2 v0 = make_float2(acc[mt][nt][0], acc[mt][nt][1]);
            float2 v1 = make_float2(acc[mt][nt][2], acc[mt][nt][3]);
            if (MODE != 1) { v0.x += bb.x; v0.y += bb.y; v1.x += bb.x; v1.y += bb.y; }
            if (MODE == 0) {
                v0.x = fmaxf(v0.x, 0.f); v0.y = fmaxf(v0.y, 0.f);
                v1.x = fmaxf(v1.x, 0.f); v1.y = fmaxf(v1.y, 0.f);
            }
            if (r0 < M) {
                if (MODE == 2) {
                    *reinterpret_cast<float2*>(&Cf[(size_t)r0 * N + gc]) = v0;
                } else {
                    *reinterpret_cast<__half2*>(&Ch[(size_t)r0 * N + gc]) =
                        __floats2half2_rn(v0.x, v0.y);
                }
            }
            if (r1 < M) {
                if (MODE == 2) {
                    *reinterpret_cast<float2*>(&Cf[(size_t)r1 * N + gc]) = v1;
                } else {
                    *reinterpret_cast<__half2*>(&Ch[(size_t)r1 * N + gc]) =
                        __floats2half2_rn(v1.x, v1.y);
                }
            }
        }
    }
}

// ---------------------------------------------------------------------------
// CSR aggregation: one warp per node, fp16 hw, fp32 accum, fp16 out.
// Edge loop unrolled x2 (proven R10/R11 body); csrsrc now sorted -> deterministic.
// ---------------------------------------------------------------------------
__global__ void __launch_bounds__(256)
agg_kernel(const __half* __restrict__ hw,
           const int* __restrict__ rowptr, const int* __restrict__ csrsrc,
           const float* __restrict__ dinv, const float* __restrict__ bias,
           __half* __restrict__ oh) {
    int warp = (blockIdx.x * blockDim.x + threadIdx.x) >> 5;
    if (warp >= N_NODES) return;
    const int lane = threadIdx.x & 31;
    const int n = warp;
    const float di = __ldg(&dinv[n]);
    const float nm = di * di;

    float acc[16];
    const uint4* self8 = reinterpret_cast<const uint4*>(hw + (size_t)n * D_HID);
    const float4* bias4 = reinterpret_cast<const float4*>(bias);
    #pragma unroll
    for (int k = 0; k < 2; k++) {
        uint4 v = __ldg(self8 + lane + 32 * k);
        const uint32_t vr[4] = {v.x, v.y, v.z, v.w};
        #pragma unroll
        for (int q = 0; q < 4; q++) {
            float2 f = __half22float2(*reinterpret_cast<const __half2*>(&vr[q]));
            float4 b0 = __ldg(bias4 + (lane + 32 * k) * 2 + (q >> 1));
            float bx = (q & 1) ? b0.z : b0.x;
            float by = (q & 1) ? b0.w : b0.y;
            acc[k * 8 + q * 2 + 0] = fmaf(f.x, nm, bx);
            acc[k * 8 + q * 2 + 1] = fmaf(f.y, nm, by);
        }
    }

    const int e0 = __ldg(&rowptr[n]);
    const int e1 = __ldg(&rowptr[n + 1]);
    int e = e0;
    for (; e + 2 <= e1; e += 2) {
        int s0 = __ldg(&csrsrc[e]);
        int s1 = __ldg(&csrsrc[e + 1]);
        float w0 = __ldg(&dinv[s0]) * di;
        float w1 = __ldg(&dinv[s1]) * di;
        const uint4* r0 = reinterpret_cast<const uint4*>(hw + (size_t)s0 * D_HID);
        const uint4* r1 = reinterpret_cast<const uint4*>(hw + (size_t)s1 * D_HID);
        uint4 v00 = __ldg(r0 + lane);
        uint4 v01 = __ldg(r0 + lane + 32);
        uint4 v10 = __ldg(r1 + lane);
        uint4 v11 = __ldg(r1 + lane + 32);
        const uint4 vv[4] = {v00, v01, v10, v11};
        const float ww[4] = {w0, w0, w1, w1};
        #pragma unroll
        for (int p = 0; p < 4; p++) {
            int k = p & 1;
            const uint32_t vr[4] = {vv[p].x, vv[p].y, vv[p].z, vv[p].w};
            #pragma unroll
            for (int q = 0; q < 4; q++) {
                float2 f = __half22float2(*reinterpret_cast<const __half2*>(&vr[q]));
                acc[k * 8 + q * 2 + 0] = fmaf(f.x, ww[p], acc[k * 8 + q * 2 + 0]);
                acc[k * 8 + q * 2 + 1] = fmaf(f.y, ww[p], acc[k * 8 + q * 2 + 1]);
            }
        }
    }
    for (; e < e1; e++) {
        int s = __ldg(&csrsrc[e]);
        float w = __ldg(&dinv[s]) * di;
        const uint4* row8 = reinterpret_cast<const uint4*>(hw + (size_t)s * D_HID);
        #pragma unroll
        for (int k = 0; k < 2; k++) {
            uint4 v = __ldg(row8 + lane + 32 * k);
            const uint32_t vr[4] = {v.x, v.y, v.z, v.w};
            #pragma unroll
            for (int q = 0; q < 4; q++) {
                float2 f = __half22float2(*reinterpret_cast<const __half2*>(&vr[q]));
                acc[k * 8 + q * 2 + 0] = fmaf(f.x, w, acc[k * 8 + q * 2 + 0]);
                acc[k * 8 + q * 2 + 1] = fmaf(f.y, w, acc[k * 8 + q * 2 + 1]);
            }
        }
    }

    #pragma unroll
    for (int k = 0; k < 2; k++) {
        size_t base = (size_t)n * D_HID + (lane + 32 * k) * 8;
        uint32_t h[4];
        #pragma unroll
        for (int q = 0; q < 4; q++) {
            __half2 p = __floats2half2_rn(acc[k * 8 + q * 2], acc[k * 8 + q * 2 + 1]);
            h[q] = *reinterpret_cast<uint32_t*>(&p);
        }
        *reinterpret_cast<uint4*>(oh + base) = make_uint4(h[0], h[1], h[2], h[3]);
    }
}

// ---------------------------------------------------------------------------
extern "C" void kernel_launch(void* const* d_in, const int* in_sizes, int n_in,
                              void* d_out, int out_size) {
    const float* x  = (const float*)d_in[0];
    const int*   ei = (const int*)  d_in[1];
    const float* W1 = (const float*)d_in[2];
    const float* b1 = (const float*)d_in[3];
    const float* Wc = (const float*)d_in[4];
    const float* bc = (const float*)d_in[5];
    const float* W2 = (const float*)d_in[6];
    const float* b2 = (const float*)d_in[7];
    float* out = (float*)d_out;

    float *dinv;
    __half *hw, *a, *b, *whi;
    int *rowcnt, *cursor, *rowptr, *bsum, *csrsrc;
    cudaGetSymbolAddress((void**)&hw,     g_hw);
    cudaGetSymbolAddress((void**)&dinv,   g_dinv);
    cudaGetSymbolAddress((void**)&a,      g_a);
    cudaGetSymbolAddress((void**)&b,      g_b);
    cudaGetSymbolAddress((void**)&whi,    g_whi);
    cudaGetSymbolAddress((void**)&rowcnt, g_rowcnt);
    cudaGetSymbolAddress((void**)&cursor, g_cursor);
    cudaGetSymbolAddress((void**)&rowptr, g_rowptr);
    cudaGetSymbolAddress((void**)&bsum,   g_bsum);
    cudaGetSymbolAddress((void**)&csrsrc, g_csrsrc);

    const int* srcI = ei;
    const int* dstI = ei + N_EDGES;

    // CSR build + dinv + deterministic row order
    hist_zero_kernel  <<<(N_NODES + 255) / 256, 256>>>(rowcnt, cursor);
    hist_kernel       <<<(N_EDGES + 255) / 256, 256>>>(dstI, rowcnt);
    scan_local_kernel <<<SCAN_NB, 1024>>>(rowcnt, rowptr, bsum);
    scan_finish_kernel<<<(N_NODES + 255) / 256, 256>>>(rowptr, bsum, rowcnt, dinv);
    fill_kernel       <<<(N_EDGES + 255) / 256, 256>>>(srcI, dstI, rowptr, cursor, csrsrc);
    sort_rows_kernel  <<<(N_NODES + 255) / 256, 256>>>(rowptr, csrsrc);

    // all weights -> transposed fp16 (1 kernel)
    conv_w_all_kernel<<<(W_TOTAL + 255) / 256, 256>>>(W1, Wc, W2, whi);

    const int GRID_M = (N_NODES + 127) / 128;

    // x -> fp16
    {
        long long n4 = (long long)N_NODES * D_IN / 4;
        conv_x_kernel<<<(int)((n4 + 255) / 256), 256>>>(x, a, n4);
    }

    // dnn1: fp16(relu(x @ W1 + b1)) -> b
    {
        dim3 g(GRID_M, D_HID / 128);
        gemm_mma_kernel<D_IN, 0><<<g, 256>>>(
            a, whi + W1T_OFF, b1, nullptr, b, N_NODES, D_HID);
    }

    const int agg_blocks = (N_NODES * 32 + 255) / 256;
    for (int l = 0; l < N_LAYERS; l++) {
        dim3 g(GRID_M, D_HID / 128);
        gemm_mma_kernel<D_HID, 1><<<g, 256>>>(
            b, whi + WCT_OFF + (size_t)l * D_HID * D_HID,
            nullptr, nullptr, hw, N_NODES, D_HID);
        agg_kernel<<<agg_blocks, 256>>>(hw, rowptr, csrsrc, dinv,
                                        bc + (size_t)l * D_HID, b);
    }

    // dnn2: out = h @ W2 + b2
    {
        dim3 g(GRID_M, D_OUT / 128);
        gemm_mma_kernel<D_HID, 2><<<g, 256>>>(
            b, whi + W2T_OFF, b2, out, nullptr, N_NODES, D_OUT);
    }
}